// round 1
// baseline (speedup 1.0000x reference)
#include <cuda_runtime.h>
#include <cstdint>

#define N_USERS  100000
#define M_ITEMS  50000
#define N_ALL    150000
#define N_EDGES  4800000
#define DIM      64
#define NELEM    (N_ALL * DIM)           // 9,600,000 floats per buffer

// Jacobi coefficients for A=B=1 (compile-time constants, match reference exactly)
// e1 = spmm(embed)
// e2 = 1.875 * spmm(e1) - 0.75 * embed
// e3 = (28/15) * spmm(e2) - 0.8 * e1
#define THETA1_K2 1.875f
#define THETA3_K2 0.75f
#define THETA1_K3 (28.0f / 15.0f)
#define THETA3_K3 0.8f

// Static scratch (allocation-free rule): 4 x 38.4 MB
__device__ float g_embed[NELEM];
__device__ float g_e1[NELEM];     // doubles as spmm1 target
__device__ float g_e2[NELEM];
__device__ float g_y[NELEM];      // spmm2 target, then reused as spmm3 target

// ---------------------------------------------------------------------------
// init: embed = concat(user, item); zero e1 (spmm1 accumulator) and y (spmm2)
// ---------------------------------------------------------------------------
__global__ void init_kernel(const float* __restrict__ user,
                            const float* __restrict__ item) {
    int i = blockIdx.x * blockDim.x + threadIdx.x;   // float4 index
    const int n4 = NELEM / 4;
    if (i >= n4) return;
    const float4* src;
    int off = i;
    if (i < (N_USERS * DIM) / 4) {
        src = (const float4*)user;
    } else {
        src = (const float4*)item;
        off = i - (N_USERS * DIM) / 4;
    }
    float4 v = src[off];
    ((float4*)g_embed)[i] = v;
    float4 z = make_float4(0.f, 0.f, 0.f, 0.f);
    ((float4*)g_e1)[i] = z;
    ((float4*)g_y)[i]  = z;
}

// ---------------------------------------------------------------------------
// spmm: y[rows[e]] += scale * vals[e] * x[cols[e]]
// 16 threads per edge, float4 per thread (64 floats = one row)
// ---------------------------------------------------------------------------
__global__ void spmm_kernel(const int*   __restrict__ rows,
                            const int*   __restrict__ cols,
                            const float* __restrict__ vals,
                            const float* __restrict__ x,
                            float*       __restrict__ y,
                            float scale) {
    long long t = (long long)blockIdx.x * blockDim.x + threadIdx.x;
    int e   = (int)(t >> 4);
    int sub = (int)(t & 15);
    if (e >= N_EDGES) return;

    int   r = __ldg(rows + e);
    int   c = __ldg(cols + e);
    float v = __ldg(vals + e) * scale;

    float4 xv = __ldg((const float4*)(x + (long long)c * DIM) + sub);
    float4 o;
    o.x = xv.x * v; o.y = xv.y * v; o.z = xv.z * v; o.w = xv.w * v;

    float* yp = y + (long long)r * DIM + sub * 4;
    asm volatile("red.global.add.v4.f32 [%0], {%1,%2,%3,%4};"
                 :: "l"(yp), "f"(o.x), "f"(o.y), "f"(o.z), "f"(o.w)
                 : "memory");
}

// ---------------------------------------------------------------------------
// ew2: e2 = y - 0.75*embed  (y holds 1.875*spmm(e1)); then zero y for spmm3
// ---------------------------------------------------------------------------
__global__ void ew2_kernel() {
    int i = blockIdx.x * blockDim.x + threadIdx.x;
    const int n4 = NELEM / 4;
    if (i >= n4) return;
    float4 yv = ((const float4*)g_y)[i];
    float4 em = ((const float4*)g_embed)[i];
    float4 r;
    r.x = yv.x - THETA3_K2 * em.x;
    r.y = yv.y - THETA3_K2 * em.y;
    r.z = yv.z - THETA3_K2 * em.z;
    r.w = yv.w - THETA3_K2 * em.w;
    ((float4*)g_e2)[i] = r;
    ((float4*)g_y)[i]  = make_float4(0.f, 0.f, 0.f, 0.f);
}

// ---------------------------------------------------------------------------
// final: e3 = y - 0.8*e1  (y holds (28/15)*spmm(e2))
//        band_stop = 0.25*(embed + e1 + e2 + e3) = 0.25*(embed + 0.2*e1 + e2 + y)
//        band_pass = tanh(0.1*embed - band_stop)
//        out[n*128 + d] = band_stop ; out[n*128 + 64 + d] = band_pass
// ---------------------------------------------------------------------------
__global__ void final_kernel(float* __restrict__ out) {
    int i = blockIdx.x * blockDim.x + threadIdx.x;   // float4 index over NELEM
    const int n4 = NELEM / 4;
    if (i >= n4) return;

    float4 em = ((const float4*)g_embed)[i];
    float4 a1 = ((const float4*)g_e1)[i];
    float4 a2 = ((const float4*)g_e2)[i];
    float4 yv = ((const float4*)g_y)[i];

    float4 bs, bp;
    bs.x = 0.25f * (em.x + 0.2f * a1.x + a2.x + yv.x);
    bs.y = 0.25f * (em.y + 0.2f * a1.y + a2.y + yv.y);
    bs.z = 0.25f * (em.z + 0.2f * a1.z + a2.z + yv.z);
    bs.w = 0.25f * (em.w + 0.2f * a1.w + a2.w + yv.w);
    bp.x = tanhf(0.1f * em.x - bs.x);
    bp.y = tanhf(0.1f * em.y - bs.y);
    bp.z = tanhf(0.1f * em.z - bs.z);
    bp.w = tanhf(0.1f * em.w - bs.w);

    // i indexes float4s over [node][64]; node = (i*4)/64 = i/16, d4 = i%16
    int node = i >> 4;
    int d4   = i & 15;
    float4* orow = (float4*)(out + (long long)node * 128);
    orow[d4]      = bs;
    orow[d4 + 16] = bp;
}

// ---------------------------------------------------------------------------
extern "C" void kernel_launch(void* const* d_in, const int* in_sizes, int n_in,
                              void* d_out, int out_size) {
    const float* user = (const float*)d_in[0];
    const float* item = (const float*)d_in[1];
    const int*   rows = (const int*)d_in[2];
    const int*   cols = (const int*)d_in[3];
    const float* vals = (const float*)d_in[4];
    float* out = (float*)d_out;

    float* embed; float* e1; float* e2; float* y;
    cudaGetSymbolAddress((void**)&embed, g_embed);
    cudaGetSymbolAddress((void**)&e1,    g_e1);
    cudaGetSymbolAddress((void**)&e2,    g_e2);
    cudaGetSymbolAddress((void**)&y,     g_y);

    const int TPB = 256;
    const int ew_blocks = (NELEM / 4 + TPB - 1) / TPB;
    const long long spmm_threads = (long long)N_EDGES * 16;
    const int spmm_blocks = (int)((spmm_threads + TPB - 1) / TPB);

    init_kernel<<<ew_blocks, TPB>>>(user, item);
    // e1 = spmm(embed)
    spmm_kernel<<<spmm_blocks, TPB>>>(rows, cols, vals, embed, e1, 1.0f);
    // y = 1.875 * spmm(e1)
    spmm_kernel<<<spmm_blocks, TPB>>>(rows, cols, vals, e1, y, THETA1_K2);
    // e2 = y - 0.75*embed ; y = 0
    ew2_kernel<<<ew_blocks, TPB>>>();
    // y = (28/15) * spmm(e2)
    spmm_kernel<<<spmm_blocks, TPB>>>(rows, cols, vals, e2, y, THETA1_K3);
    // e3 = y - 0.8*e1 ; combine ; write out
    final_kernel<<<ew_blocks, TPB>>>(out);
}

// round 2
// speedup vs baseline: 2.0238x; 2.0238x over previous
#include <cuda_runtime.h>
#include <cstdint>

#define N_USERS  100000
#define M_ITEMS  50000
#define N_ALL    150000
#define N_EDGES  4800000
#define DIM      64
#define NELEM    (N_ALL * DIM)

// Jacobi coefficients for A=B=1
#define THETA1_K2 1.875f
#define THETA3_K2 0.75f
#define THETA1_K3 (28.0f / 15.0f)
#define THETA3_K3 0.8f

#define SCAN_BLK 1024
#define N_SCAN_BLOCKS ((N_ALL + SCAN_BLK - 1) / SCAN_BLK)   // 147

// Static scratch (allocation-free rule)
__device__ float g_embed[NELEM];
__device__ float g_e1[NELEM];
__device__ float g_e2[NELEM];
__device__ int   g_count[N_ALL];
__device__ int   g_start[N_ALL + 1];
__device__ int   g_cursor[N_ALL];
__device__ int2  g_epack[N_EDGES];          // (col, val-bits) in CSR order
__device__ int   g_bsum[N_SCAN_BLOCKS];

// ---------------------------------------------------------------------------
// init: embed = concat(user,item) (float4 copy); zero row counters
// ---------------------------------------------------------------------------
__global__ void init_kernel(const float* __restrict__ user,
                            const float* __restrict__ item) {
    int i = blockIdx.x * blockDim.x + threadIdx.x;
    const int n4 = NELEM / 4;
    if (i < n4) {
        float4 v;
        if (i < (N_USERS * DIM) / 4)
            v = ((const float4*)user)[i];
        else
            v = ((const float4*)item)[i - (N_USERS * DIM) / 4];
        ((float4*)g_embed)[i] = v;
    }
    if (i < N_ALL) g_count[i] = 0;
}

// ---------------------------------------------------------------------------
// histogram of rows
// ---------------------------------------------------------------------------
__global__ void hist_kernel(const int* __restrict__ rows) {
    int e = blockIdx.x * blockDim.x + threadIdx.x;
    if (e < N_EDGES) atomicAdd(&g_count[__ldg(rows + e)], 1);
}

// ---------------------------------------------------------------------------
// scan stage 1: per-block exclusive scan of counts, block totals to g_bsum
// ---------------------------------------------------------------------------
__global__ void scan1_kernel() {
    __shared__ int sh[SCAN_BLK];
    int t = threadIdx.x;
    int i = blockIdx.x * SCAN_BLK + t;
    int v = (i < N_ALL) ? g_count[i] : 0;
    sh[t] = v;
    __syncthreads();
    for (int o = 1; o < SCAN_BLK; o <<= 1) {
        int a = (t >= o) ? sh[t - o] : 0;
        __syncthreads();
        sh[t] += a;
        __syncthreads();
    }
    if (i < N_ALL) g_start[i] = sh[t] - v;          // exclusive
    if (t == SCAN_BLK - 1) g_bsum[blockIdx.x] = sh[t];
}

// scan stage 2: serial exclusive scan of 147 block sums (trivial)
__global__ void scan2_kernel() {
    if (threadIdx.x == 0) {
        int run = 0;
        for (int b = 0; b < N_SCAN_BLOCKS; b++) {
            int v = g_bsum[b];
            g_bsum[b] = run;
            run += v;
        }
    }
}

// scan stage 3: add block offset; init cursors; set sentinel
__global__ void scan3_kernel() {
    int i = blockIdx.x * SCAN_BLK + threadIdx.x;
    if (i < N_ALL) {
        int s = g_start[i] + g_bsum[blockIdx.x];
        g_start[i]  = s;
        g_cursor[i] = s;
    }
    if (i == 0) g_start[N_ALL] = N_EDGES;
}

// ---------------------------------------------------------------------------
// scatter edges into CSR order: g_epack[pos] = (col, val)
// ---------------------------------------------------------------------------
__global__ void scatter_kernel(const int*   __restrict__ rows,
                               const int*   __restrict__ cols,
                               const float* __restrict__ vals) {
    int e = blockIdx.x * blockDim.x + threadIdx.x;
    if (e >= N_EDGES) return;
    int r = __ldg(rows + e);
    int pos = atomicAdd(&g_cursor[r], 1);
    g_epack[pos] = make_int2(__ldg(cols + e), __float_as_int(__ldg(vals + e)));
}

// ---------------------------------------------------------------------------
// gather spmm, warp per row: y[r] = scale * sum_j val_j * x[col_j]
// ---------------------------------------------------------------------------
__global__ void spmm1_kernel() {
    int w = (blockIdx.x * blockDim.x + threadIdx.x) >> 5;
    int lane = threadIdx.x & 31;
    if (w >= N_ALL) return;
    int s = g_start[w], e = g_start[w + 1];
    float ax = 0.f, ay = 0.f;
    const float* x = g_embed;
    for (int j = s; j < e; j++) {
        int2 p = g_epack[j];                       // broadcast (1 req/warp)
        float v = __int_as_float(p.y);
        float2 xv = __ldg((const float2*)(x + (long long)p.x * DIM) + lane);
        ax += v * xv.x; ay += v * xv.y;
    }
    ((float2*)(g_e1 + (long long)w * DIM))[lane] = make_float2(ax, ay);
}

// spmm2 + fused epilogue: e2 = 1.875*spmm(e1) - 0.75*embed
__global__ void spmm2_kernel() {
    int w = (blockIdx.x * blockDim.x + threadIdx.x) >> 5;
    int lane = threadIdx.x & 31;
    if (w >= N_ALL) return;
    int s = g_start[w], e = g_start[w + 1];
    float ax = 0.f, ay = 0.f;
    const float* x = g_e1;
    for (int j = s; j < e; j++) {
        int2 p = g_epack[j];
        float v = __int_as_float(p.y);
        float2 xv = __ldg((const float2*)(x + (long long)p.x * DIM) + lane);
        ax += v * xv.x; ay += v * xv.y;
    }
    float2 em = ((const float2*)(g_embed + (long long)w * DIM))[lane];
    float2 r;
    r.x = THETA1_K2 * ax - THETA3_K2 * em.x;
    r.y = THETA1_K2 * ay - THETA3_K2 * em.y;
    ((float2*)(g_e2 + (long long)w * DIM))[lane] = r;
}

// spmm3 + fused final epilogue:
//   e3 = (28/15)*spmm(e2) - 0.8*e1
//   bs = 0.25*(embed + e1 + e2 + e3);  bp = tanh(0.1*embed - bs)
//   out[r*128 + d] = bs ; out[r*128 + 64 + d] = bp
__global__ void spmm3_kernel(float* __restrict__ out) {
    int w = (blockIdx.x * blockDim.x + threadIdx.x) >> 5;
    int lane = threadIdx.x & 31;
    if (w >= N_ALL) return;
    int s = g_start[w], e = g_start[w + 1];
    float ax = 0.f, ay = 0.f;
    const float* x = g_e2;
    for (int j = s; j < e; j++) {
        int2 p = g_epack[j];
        float v = __int_as_float(p.y);
        float2 xv = __ldg((const float2*)(x + (long long)p.x * DIM) + lane);
        ax += v * xv.x; ay += v * xv.y;
    }
    float2 em = ((const float2*)(g_embed + (long long)w * DIM))[lane];
    float2 a1 = ((const float2*)(g_e1   + (long long)w * DIM))[lane];
    float2 a2 = ((const float2*)(g_e2   + (long long)w * DIM))[lane];
    // bs = 0.25*(em + e1 + e2 + e3), e3 = (28/15)*acc - 0.8*e1
    float2 bs, bp;
    bs.x = 0.25f * (em.x + 0.2f * a1.x + a2.x + THETA1_K3 * ax);
    bs.y = 0.25f * (em.y + 0.2f * a1.y + a2.y + THETA1_K3 * ay);
    bp.x = tanhf(0.1f * em.x - bs.x);
    bp.y = tanhf(0.1f * em.y - bs.y);
    float2* orow = (float2*)(out + (long long)w * 128);
    orow[lane]      = bs;
    orow[lane + 32] = bp;
}

// ---------------------------------------------------------------------------
extern "C" void kernel_launch(void* const* d_in, const int* in_sizes, int n_in,
                              void* d_out, int out_size) {
    const float* user = (const float*)d_in[0];
    const float* item = (const float*)d_in[1];
    const int*   rows = (const int*)d_in[2];
    const int*   cols = (const int*)d_in[3];
    const float* vals = (const float*)d_in[4];
    float* out = (float*)d_out;

    const int TPB = 256;
    const int init_blocks = (NELEM / 4 + TPB - 1) / TPB;          // covers N_ALL too
    const int edge_blocks = (N_EDGES + TPB - 1) / TPB;
    const int spmm_blocks = ((N_ALL * 32) + TPB - 1) / TPB;

    init_kernel<<<init_blocks, TPB>>>(user, item);
    hist_kernel<<<edge_blocks, TPB>>>(rows);
    scan1_kernel<<<N_SCAN_BLOCKS, SCAN_BLK>>>();
    scan2_kernel<<<1, 32>>>();
    scan3_kernel<<<N_SCAN_BLOCKS, SCAN_BLK>>>();
    scatter_kernel<<<edge_blocks, TPB>>>(rows, cols, vals);
    spmm1_kernel<<<spmm_blocks, TPB>>>();
    spmm2_kernel<<<spmm_blocks, TPB>>>();
    spmm3_kernel<<<spmm_blocks, TPB>>>(out);
}

// round 3
// speedup vs baseline: 2.3629x; 1.1675x over previous
#include <cuda_runtime.h>
#include <cuda_fp16.h>
#include <cstdint>

#define N_USERS  100000
#define M_ITEMS  50000
#define N_ALL    150000
#define N_EDGES  4800000
#define DIM      64
#define NELEM    (N_ALL * DIM)

// Jacobi coefficients for A=B=1
#define THETA1_K2 1.875f
#define THETA3_K2 0.75f
#define THETA1_K3 (28.0f / 15.0f)

#define SCAN_BLK 1024
#define N_SCAN_BLOCKS ((N_ALL + SCAN_BLK - 1) / SCAN_BLK)   // 147

// Static scratch (allocation-free rule)
__device__ float  g_embed[NELEM];       // fp32 embed (epilogue operand)
__device__ __half g_hx[3][NELEM];       // fp16 gather shadows: embed, e1, e2
__device__ int    g_count[N_ALL];       // zero-invariant between calls
__device__ int    g_start[N_ALL + 1];
__device__ int    g_cursor[N_ALL];
__device__ int2   g_epack[N_EDGES];     // (col, val-bits) CSR-ordered
__device__ int    g_bsum[N_SCAN_BLOCKS];

// ---------------------------------------------------------------------------
// init: embed = concat(user,item) fp32 + fp16 shadow; fused row histogram
// g_count is zero on entry (BSS at load, re-zeroed by scan1 every call)
// ---------------------------------------------------------------------------
__global__ void init_kernel(const float* __restrict__ user,
                            const float* __restrict__ item,
                            const int*   __restrict__ rows) {
    int i = blockIdx.x * blockDim.x + threadIdx.x;   // float4 index
    const int n4 = NELEM / 4;                        // 2,400,000
    if (i < n4) {
        float4 v;
        if (i < (N_USERS * DIM) / 4)
            v = ((const float4*)user)[i];
        else
            v = ((const float4*)item)[i - (N_USERS * DIM) / 4];
        ((float4*)g_embed)[i] = v;
        __half2 h0 = __floats2half2_rn(v.x, v.y);
        __half2 h1 = __floats2half2_rn(v.z, v.w);
        ((__half2*)g_hx[0])[2 * i]     = h0;
        ((__half2*)g_hx[0])[2 * i + 1] = h1;
        // fused histogram: 2 edges per thread (N_EDGES == 2*n4)
        atomicAdd(&g_count[__ldg(rows + i)], 1);
        atomicAdd(&g_count[__ldg(rows + i + n4)], 1);
    }
}

// ---------------------------------------------------------------------------
// scan stage 1: per-block exclusive scan of counts; re-zero counts
// ---------------------------------------------------------------------------
__global__ void scan1_kernel() {
    __shared__ int sh[SCAN_BLK];
    int t = threadIdx.x;
    int i = blockIdx.x * SCAN_BLK + t;
    int v = (i < N_ALL) ? g_count[i] : 0;
    if (i < N_ALL) g_count[i] = 0;                  // restore zero-invariant
    sh[t] = v;
    __syncthreads();
    for (int o = 1; o < SCAN_BLK; o <<= 1) {
        int a = (t >= o) ? sh[t - o] : 0;
        __syncthreads();
        sh[t] += a;
        __syncthreads();
    }
    if (i < N_ALL) g_start[i] = sh[t] - v;          // exclusive
    if (t == SCAN_BLK - 1) g_bsum[blockIdx.x] = sh[t];
}

// scan stage 2: parallel exclusive scan of 147 block sums (one block)
__global__ void scan2_kernel() {
    __shared__ int sh[256];
    int t = threadIdx.x;
    int v = (t < N_SCAN_BLOCKS) ? g_bsum[t] : 0;
    sh[t] = v;
    __syncthreads();
    for (int o = 1; o < 256; o <<= 1) {
        int a = (t >= o) ? sh[t - o] : 0;
        __syncthreads();
        sh[t] += a;
        __syncthreads();
    }
    if (t < N_SCAN_BLOCKS) g_bsum[t] = sh[t] - v;   // exclusive
}

// scan stage 3: add block offsets; init cursors; sentinel
__global__ void scan3_kernel() {
    int i = blockIdx.x * SCAN_BLK + threadIdx.x;
    if (i < N_ALL) {
        int s = g_start[i] + g_bsum[blockIdx.x];
        g_start[i]  = s;
        g_cursor[i] = s;
    }
    if (i == 0) g_start[N_ALL] = N_EDGES;
}

// ---------------------------------------------------------------------------
// scatter edges into CSR order
// ---------------------------------------------------------------------------
__global__ void scatter_kernel(const int*   __restrict__ rows,
                               const int*   __restrict__ cols,
                               const float* __restrict__ vals) {
    int e = blockIdx.x * blockDim.x + threadIdx.x;
    if (e >= N_EDGES) return;
    int r = __ldg(rows + e);
    int pos = atomicAdd(&g_cursor[r], 1);
    g_epack[pos] = make_int2(__ldg(cols + e), __float_as_int(__ldg(vals + e)));
}

// ---------------------------------------------------------------------------
// warp-per-row gather SpMM core over fp16 shadow x: acc = sum val_j * x[col_j]
// ---------------------------------------------------------------------------
__device__ __forceinline__ float2 spmm_row(const __half* __restrict__ hx,
                                           int s, int e, int lane) {
    float ax = 0.f, ay = 0.f;
    for (int j = s; j < e; j++) {
        int2 p = __ldg(&g_epack[j]);               // broadcast per warp
        float v = __int_as_float(p.y);
        __half2 hv = __ldg((const __half2*)(hx + (long long)p.x * DIM) + lane);
        float2 xv = __half22float2(hv);
        ax += v * xv.x; ay += v * xv.y;
    }
    return make_float2(ax, ay);
}

// spmm1: e1 = spmm(embed)  -> fp16 shadow only
__global__ void spmm1_kernel() {
    int w = (blockIdx.x * blockDim.x + threadIdx.x) >> 5;
    int lane = threadIdx.x & 31;
    if (w >= N_ALL) return;
    float2 a = spmm_row(g_hx[0], g_start[w], g_start[w + 1], lane);
    ((__half2*)(g_hx[1] + (long long)w * DIM))[lane] = __floats2half2_rn(a.x, a.y);
}

// spmm2: e2 = 1.875*spmm(e1) - 0.75*embed  -> fp16 shadow only
__global__ void spmm2_kernel() {
    int w = (blockIdx.x * blockDim.x + threadIdx.x) >> 5;
    int lane = threadIdx.x & 31;
    if (w >= N_ALL) return;
    float2 a = spmm_row(g_hx[1], g_start[w], g_start[w + 1], lane);
    float2 em = ((const float2*)(g_embed + (long long)w * DIM))[lane];
    float rx = THETA1_K2 * a.x - THETA3_K2 * em.x;
    float ry = THETA1_K2 * a.y - THETA3_K2 * em.y;
    ((__half2*)(g_hx[2] + (long long)w * DIM))[lane] = __floats2half2_rn(rx, ry);
}

// spmm3 + final epilogue:
//   e3 = (28/15)*spmm(e2) - 0.8*e1
//   bs = 0.25*(embed + 0.2*e1 + e2 + (28/15)*acc);  bp = tanh(0.1*embed - bs)
__global__ void spmm3_kernel(float* __restrict__ out) {
    int w = (blockIdx.x * blockDim.x + threadIdx.x) >> 5;
    int lane = threadIdx.x & 31;
    if (w >= N_ALL) return;
    float2 a = spmm_row(g_hx[2], g_start[w], g_start[w + 1], lane);
    float2 em = ((const float2*)(g_embed + (long long)w * DIM))[lane];
    float2 a1 = __half22float2(((const __half2*)(g_hx[1] + (long long)w * DIM))[lane]);
    float2 a2 = __half22float2(((const __half2*)(g_hx[2] + (long long)w * DIM))[lane]);
    float2 bs, bp;
    bs.x = 0.25f * (em.x + 0.2f * a1.x + a2.x + THETA1_K3 * a.x);
    bs.y = 0.25f * (em.y + 0.2f * a1.y + a2.y + THETA1_K3 * a.y);
    bp.x = tanhf(0.1f * em.x - bs.x);
    bp.y = tanhf(0.1f * em.y - bs.y);
    float2* orow = (float2*)(out + (long long)w * 128);
    orow[lane]      = bs;
    orow[lane + 32] = bp;
}

// ---------------------------------------------------------------------------
extern "C" void kernel_launch(void* const* d_in, const int* in_sizes, int n_in,
                              void* d_out, int out_size) {
    const float* user = (const float*)d_in[0];
    const float* item = (const float*)d_in[1];
    const int*   rows = (const int*)d_in[2];
    const int*   cols = (const int*)d_in[3];
    const float* vals = (const float*)d_in[4];
    float* out = (float*)d_out;

    const int TPB = 256;
    const int init_blocks = (NELEM / 4 + TPB - 1) / TPB;
    const int edge_blocks = (N_EDGES + TPB - 1) / TPB;
    const int spmm_blocks = ((N_ALL * 32) + TPB - 1) / TPB;

    init_kernel<<<init_blocks, TPB>>>(user, item, rows);
    scan1_kernel<<<N_SCAN_BLOCKS, SCAN_BLK>>>();
    scan2_kernel<<<1, 256>>>();
    scan3_kernel<<<N_SCAN_BLOCKS, SCAN_BLK>>>();
    scatter_kernel<<<edge_blocks, TPB>>>(rows, cols, vals);
    spmm1_kernel<<<spmm_blocks, TPB>>>();
    spmm2_kernel<<<spmm_blocks, TPB>>>();
    spmm3_kernel<<<spmm_blocks, TPB>>>(out);
}

// round 4
// speedup vs baseline: 2.4251x; 1.0263x over previous
#include <cuda_runtime.h>
#include <cuda_fp16.h>
#include <cstdint>

#define N_USERS  100000
#define M_ITEMS  50000
#define N_ALL    150000
#define N_EDGES  4800000
#define DIM      64
#define NELEM    (N_ALL * DIM)

// Jacobi coefficients for A=B=1
#define THETA1_K2 1.875f
#define THETA3_K2 0.75f
#define THETA1_K3 (28.0f / 15.0f)

#define SCAN_BLK 1024
#define N_SCAN_BLOCKS ((N_ALL + SCAN_BLK - 1) / SCAN_BLK)   // 147

// Static scratch (allocation-free rule)
__device__ __align__(16) float  g_embed[NELEM];   // fp32 embed
__device__ __align__(16) float  g_e2f[NELEM];     // fp32 e2 (epilogue operand)
__device__ __align__(16) __half g_hx[3][NELEM];   // fp16 gather shadows: embed,e1,e2
__device__ int   g_count[N_ALL];                  // zero-invariant between calls
__device__ int   g_start[N_ALL + 1];
__device__ int   g_cursor[N_ALL];
__device__ __align__(8) int2 g_epack[N_EDGES];    // (col, val-bits) CSR-ordered
__device__ int   g_bsum[N_SCAN_BLOCKS];

// ---------------------------------------------------------------------------
// init: embed = concat(user,item) fp32 + fp16 shadow; fused row histogram
// ---------------------------------------------------------------------------
__global__ void init_kernel(const float* __restrict__ user,
                            const float* __restrict__ item,
                            const int*   __restrict__ rows) {
    int i = blockIdx.x * blockDim.x + threadIdx.x;   // float4 index
    const int n4 = NELEM / 4;                        // 2,400,000
    if (i < n4) {
        float4 v;
        if (i < (N_USERS * DIM) / 4)
            v = ((const float4*)user)[i];
        else
            v = ((const float4*)item)[i - (N_USERS * DIM) / 4];
        ((float4*)g_embed)[i] = v;
        __half2 h0 = __floats2half2_rn(v.x, v.y);
        __half2 h1 = __floats2half2_rn(v.z, v.w);
        ((__half2*)g_hx[0])[2 * i]     = h0;
        ((__half2*)g_hx[0])[2 * i + 1] = h1;
        atomicAdd(&g_count[__ldg(rows + i)], 1);
        atomicAdd(&g_count[__ldg(rows + i + n4)], 1);
    }
}

// ---------------------------------------------------------------------------
// scan stage 1: per-block exclusive scan of counts; re-zero counts
// ---------------------------------------------------------------------------
__global__ void scan1_kernel() {
    __shared__ int sh[SCAN_BLK];
    int t = threadIdx.x;
    int i = blockIdx.x * SCAN_BLK + t;
    int v = (i < N_ALL) ? g_count[i] : 0;
    if (i < N_ALL) g_count[i] = 0;
    sh[t] = v;
    __syncthreads();
    for (int o = 1; o < SCAN_BLK; o <<= 1) {
        int a = (t >= o) ? sh[t - o] : 0;
        __syncthreads();
        sh[t] += a;
        __syncthreads();
    }
    if (i < N_ALL) g_start[i] = sh[t] - v;
    if (t == SCAN_BLK - 1) g_bsum[blockIdx.x] = sh[t];
}

// scan stage 2: parallel exclusive scan of 147 block sums
__global__ void scan2_kernel() {
    __shared__ int sh[256];
    int t = threadIdx.x;
    int v = (t < N_SCAN_BLOCKS) ? g_bsum[t] : 0;
    sh[t] = v;
    __syncthreads();
    for (int o = 1; o < 256; o <<= 1) {
        int a = (t >= o) ? sh[t - o] : 0;
        __syncthreads();
        sh[t] += a;
        __syncthreads();
    }
    if (t < N_SCAN_BLOCKS) g_bsum[t] = sh[t] - v;
}

// scan stage 3: add block offsets; init cursors; sentinel
__global__ void scan3_kernel() {
    int i = blockIdx.x * SCAN_BLK + threadIdx.x;
    if (i < N_ALL) {
        int s = g_start[i] + g_bsum[blockIdx.x];
        g_start[i]  = s;
        g_cursor[i] = s;
    }
    if (i == 0) g_start[N_ALL] = N_EDGES;
}

// ---------------------------------------------------------------------------
// scatter edges into CSR order
// ---------------------------------------------------------------------------
__global__ void scatter_kernel(const int*   __restrict__ rows,
                               const int*   __restrict__ cols,
                               const float* __restrict__ vals) {
    int e = blockIdx.x * blockDim.x + threadIdx.x;
    if (e >= N_EDGES) return;
    int r = __ldg(rows + e);
    int pos = atomicAdd(&g_cursor[r], 1);
    g_epack[pos] = make_int2(__ldg(cols + e), __float_as_int(__ldg(vals + e)));
}

// ---------------------------------------------------------------------------
// SpMM core: warp per row, 8 lanes per edge-row (16 B each), 4 edges / iter.
// lane = g*8 + sl ; lane covers dims sl*8..sl*8+7 of edge (j+g).
// After the loop, acc is reduced across the 4 groups via shfl_xor.
// ---------------------------------------------------------------------------
__device__ __forceinline__ void edge_accum(const __half* __restrict__ hx,
                                           int2 p, int sl, float acc[8]) {
    float v = __int_as_float(p.y);
    uint4 q = __ldg((const uint4*)(hx + (size_t)p.x * DIM) + sl);
    float2 f;
    f = __half22float2(*(__half2*)&q.x); acc[0] += v * f.x; acc[1] += v * f.y;
    f = __half22float2(*(__half2*)&q.y); acc[2] += v * f.x; acc[3] += v * f.y;
    f = __half22float2(*(__half2*)&q.z); acc[4] += v * f.x; acc[5] += v * f.y;
    f = __half22float2(*(__half2*)&q.w); acc[6] += v * f.x; acc[7] += v * f.y;
}

__device__ __forceinline__ void spmm_row(const __half* __restrict__ hx,
                                         int s, int e, int g, int sl,
                                         float acc[8]) {
#pragma unroll
    for (int k = 0; k < 8; k++) acc[k] = 0.f;
    int n  = e - s;
    int n4 = n & ~3;
#pragma unroll 2
    for (int j = s; j < s + n4; j += 4) {
        int2 p = __ldg(&g_epack[j + g]);
        edge_accum(hx, p, sl, acc);
    }
    int rem = n - n4;
    if (g < rem) {
        int2 p = __ldg(&g_epack[s + n4 + g]);
        edge_accum(hx, p, sl, acc);
    }
#pragma unroll
    for (int k = 0; k < 8; k++) {
        acc[k] += __shfl_xor_sync(0xFFFFFFFFu, acc[k], 8);
        acc[k] += __shfl_xor_sync(0xFFFFFFFFu, acc[k], 16);
    }
}

__device__ __forceinline__ uint4 pack_half8(const float a[8]) {
    __half2 h[4];
    h[0] = __floats2half2_rn(a[0], a[1]);
    h[1] = __floats2half2_rn(a[2], a[3]);
    h[2] = __floats2half2_rn(a[4], a[5]);
    h[3] = __floats2half2_rn(a[6], a[7]);
    return *(uint4*)h;
}

// spmm1: e1 = spmm(embed) -> fp16 shadow
__global__ void spmm1_kernel() {
    int w = (blockIdx.x * blockDim.x + threadIdx.x) >> 5;
    int lane = threadIdx.x & 31;
    if (w >= N_ALL) return;
    int g = lane >> 3, sl = lane & 7;
    float acc[8];
    spmm_row(g_hx[0], g_start[w], g_start[w + 1], g, sl, acc);
    if (g == 0)
        ((uint4*)(g_hx[1] + (size_t)w * DIM))[sl] = pack_half8(acc);
}

// spmm2: e2 = 1.875*spmm(e1) - 0.75*embed -> fp16 shadow + fp32 copy
__global__ void spmm2_kernel() {
    int w = (blockIdx.x * blockDim.x + threadIdx.x) >> 5;
    int lane = threadIdx.x & 31;
    if (w >= N_ALL) return;
    int g = lane >> 3, sl = lane & 7;
    float acc[8];
    spmm_row(g_hx[1], g_start[w], g_start[w + 1], g, sl, acc);
    if (g < 2) {
        const float4* emp = (const float4*)(g_embed + (size_t)w * DIM);
        float4 em0 = emp[2 * sl], em1 = emp[2 * sl + 1];
        float r[8];
        r[0] = THETA1_K2 * acc[0] - THETA3_K2 * em0.x;
        r[1] = THETA1_K2 * acc[1] - THETA3_K2 * em0.y;
        r[2] = THETA1_K2 * acc[2] - THETA3_K2 * em0.z;
        r[3] = THETA1_K2 * acc[3] - THETA3_K2 * em0.w;
        r[4] = THETA1_K2 * acc[4] - THETA3_K2 * em1.x;
        r[5] = THETA1_K2 * acc[5] - THETA3_K2 * em1.y;
        r[6] = THETA1_K2 * acc[6] - THETA3_K2 * em1.z;
        r[7] = THETA1_K2 * acc[7] - THETA3_K2 * em1.w;
        if (g == 0) {
            ((uint4*)(g_hx[2] + (size_t)w * DIM))[sl] = pack_half8(r);
        } else {
            float4* e2p = (float4*)(g_e2f + (size_t)w * DIM);
            e2p[2 * sl]     = make_float4(r[0], r[1], r[2], r[3]);
            e2p[2 * sl + 1] = make_float4(r[4], r[5], r[6], r[7]);
        }
    }
}

// spmm3 + final epilogue:
//   bs = 0.25*(embed + 0.2*e1 + e2 + (28/15)*acc);  bp = tanh(0.1*embed - bs)
//   out[w*128 + d] = bs ; out[w*128 + 64 + d] = bp
__global__ void spmm3_kernel(float* __restrict__ out) {
    int w = (blockIdx.x * blockDim.x + threadIdx.x) >> 5;
    int lane = threadIdx.x & 31;
    if (w >= N_ALL) return;
    int g = lane >> 3, sl = lane & 7;
    float acc[8];
    spmm_row(g_hx[2], g_start[w], g_start[w + 1], g, sl, acc);
    if (g < 2) {
        const float4* emp = (const float4*)(g_embed + (size_t)w * DIM);
        const float4* a2p = (const float4*)(g_e2f  + (size_t)w * DIM);
        float4 em0 = emp[2 * sl], em1 = emp[2 * sl + 1];
        float4 a20 = a2p[2 * sl], a21 = a2p[2 * sl + 1];
        uint4 a1q = ((const uint4*)(g_hx[1] + (size_t)w * DIM))[sl];
        float a1[8];
        {
            float2 f;
            f = __half22float2(*(__half2*)&a1q.x); a1[0] = f.x; a1[1] = f.y;
            f = __half22float2(*(__half2*)&a1q.y); a1[2] = f.x; a1[3] = f.y;
            f = __half22float2(*(__half2*)&a1q.z); a1[4] = f.x; a1[5] = f.y;
            f = __half22float2(*(__half2*)&a1q.w); a1[6] = f.x; a1[7] = f.y;
        }
        float em[8] = {em0.x, em0.y, em0.z, em0.w, em1.x, em1.y, em1.z, em1.w};
        float a2[8] = {a20.x, a20.y, a20.z, a20.w, a21.x, a21.y, a21.z, a21.w};
        float bs[8];
#pragma unroll
        for (int k = 0; k < 8; k++)
            bs[k] = 0.25f * (em[k] + 0.2f * a1[k] + a2[k] + THETA1_K3 * acc[k]);
        float4* orow = (float4*)(out + (size_t)w * 128);
        if (g == 0) {
            orow[2 * sl]     = make_float4(bs[0], bs[1], bs[2], bs[3]);
            orow[2 * sl + 1] = make_float4(bs[4], bs[5], bs[6], bs[7]);
        } else {
            float bp[8];
#pragma unroll
            for (int k = 0; k < 8; k++)
                bp[k] = tanhf(0.1f * em[k] - bs[k]);
            orow[16 + 2 * sl] = make_float4(bp[0], bp[1], bp[2], bp[3]);
            orow[17 + 2 * sl] = make_float4(bp[4], bp[5], bp[6], bp[7]);
        }
    }
}

// ---------------------------------------------------------------------------
extern "C" void kernel_launch(void* const* d_in, const int* in_sizes, int n_in,
                              void* d_out, int out_size) {
    const float* user = (const float*)d_in[0];
    const float* item = (const float*)d_in[1];
    const int*   rows = (const int*)d_in[2];
    const int*   cols = (const int*)d_in[3];
    const float* vals = (const float*)d_in[4];
    float* out = (float*)d_out;

    const int TPB = 256;
    const int init_blocks = (NELEM / 4 + TPB - 1) / TPB;
    const int edge_blocks = (N_EDGES + TPB - 1) / TPB;
    const int spmm_blocks = ((N_ALL * 32) + TPB - 1) / TPB;

    init_kernel<<<init_blocks, TPB>>>(user, item, rows);
    scan1_kernel<<<N_SCAN_BLOCKS, SCAN_BLK>>>();
    scan2_kernel<<<1, 256>>>();
    scan3_kernel<<<N_SCAN_BLOCKS, SCAN_BLK>>>();
    scatter_kernel<<<edge_blocks, TPB>>>(rows, cols, vals);
    spmm1_kernel<<<spmm_blocks, TPB>>>();
    spmm2_kernel<<<spmm_blocks, TPB>>>();
    spmm3_kernel<<<spmm_blocks, TPB>>>(out);
}